// round 2
// baseline (speedup 1.0000x reference)
#include <cuda_runtime.h>
#include <math.h>

#define SQ   2048
#define DIM  1024
#define NH   16
#define HD   64
#define FACT 16

// ---- scratch (device globals: the sanctioned no-alloc scratch path) ----
__device__ float g_Q[NH * SQ * HD];             // 8 MB  [h][s][hd]
__device__ float g_K[NH * SQ * HD];             // 8 MB
__device__ float g_V[NH * SQ * HD];             // 8 MB
__device__ float g_scores[(size_t)NH * SQ * SQ]; // 256 MB [h][q][k]
__device__ float g_vsum[NH * HD];
__device__ float g_attn[SQ * DIM];              // 8 MB  [s][d]

// ============================================================
// Generic fp32 GEMM: C[M,N] = A[M,K] @ B[K,N] + bias[N]
// 128x128 tile, BK=8, 256 threads, 8x8 microtile.
// remap!=0 -> write C in [h][row][t] layout (h=col/64, t=col%64)
// ============================================================
__global__ __launch_bounds__(256) void sgemm_bias(
    const float* __restrict__ A, const float* __restrict__ B,
    const float* __restrict__ bias, float* __restrict__ C,
    int M, int N, int K, int remap)
{
    __shared__ float As[8][128];
    __shared__ float Bs[8][128];

    const int tid  = threadIdx.x;
    const int r0   = blockIdx.y * 128;
    const int n0   = blockIdx.x * 128;
    const int trow = tid / 16;          // 0..15
    const int tcol = tid % 16;          // 0..15

    const int arow = tid >> 1;          // 0..127
    const int ac4  = (tid & 1) * 4;     // 0 or 4
    const int brow = tid >> 5;          // 0..7
    const int bc4  = (tid & 31) * 4;    // 0..124

    float acc[8][8];
#pragma unroll
    for (int i = 0; i < 8; i++)
#pragma unroll
        for (int j = 0; j < 8; j++) acc[i][j] = 0.0f;

    for (int k0 = 0; k0 < K; k0 += 8) {
        float4 av = *(const float4*)&A[(size_t)(r0 + arow) * K + k0 + ac4];
        As[ac4 + 0][arow] = av.x;
        As[ac4 + 1][arow] = av.y;
        As[ac4 + 2][arow] = av.z;
        As[ac4 + 3][arow] = av.w;
        *(float4*)&Bs[brow][bc4] =
            *(const float4*)&B[(size_t)(k0 + brow) * N + n0 + bc4];
        __syncthreads();

#pragma unroll
        for (int kk = 0; kk < 8; kk++) {
            float a[8], b[8];
            *(float4*)(a)     = *(const float4*)&As[kk][trow * 8];
            *(float4*)(a + 4) = *(const float4*)&As[kk][trow * 8 + 4];
            *(float4*)(b)     = *(const float4*)&Bs[kk][tcol * 8];
            *(float4*)(b + 4) = *(const float4*)&Bs[kk][tcol * 8 + 4];
#pragma unroll
            for (int i = 0; i < 8; i++)
#pragma unroll
                for (int j = 0; j < 8; j++)
                    acc[i][j] = fmaf(a[i], b[j], acc[i][j]);
        }
        __syncthreads();
    }

#pragma unroll
    for (int i = 0; i < 8; i++) {
        const int row = r0 + trow * 8 + i;
#pragma unroll
        for (int j0 = 0; j0 < 8; j0 += 4) {
            const int col = n0 + tcol * 8 + j0;
            float4 o;
            o.x = acc[i][j0 + 0] + bias[col + 0];
            o.y = acc[i][j0 + 1] + bias[col + 1];
            o.z = acc[i][j0 + 2] + bias[col + 2];
            o.w = acc[i][j0 + 3] + bias[col + 3];
            if (remap) {
                const int h = col >> 6;
                const int t = col & 63;
                *(float4*)&C[((size_t)h * SQ + row) * HD + t] = o;
            } else {
                *(float4*)&C[(size_t)row * N + col] = o;
            }
        }
    }
}

// ============================================================
// Scores: g_scores[h][q][k] = (Q[h][q] . K[h][k]) / 8
// 128x128 tile per block, full K-dim=64 in two 32-deep passes.
// ============================================================
__global__ __launch_bounds__(256) void scores_kernel()
{
    __shared__ float Qs[32][128];
    __shared__ float Ks[32][128];

    const int h  = blockIdx.z;
    const float* Qh = g_Q + (size_t)h * SQ * HD;
    const float* Kh = g_K + (size_t)h * SQ * HD;
    float* Sc = g_scores + (size_t)h * SQ * SQ;

    const int q0 = blockIdx.y * 128;
    const int k0 = blockIdx.x * 128;
    const int tid  = threadIdx.x;
    const int trow = tid / 16;
    const int tcol = tid % 16;

    float acc[8][8];
#pragma unroll
    for (int i = 0; i < 8; i++)
#pragma unroll
        for (int j = 0; j < 8; j++) acc[i][j] = 0.0f;

    for (int d0 = 0; d0 < HD; d0 += 32) {
#pragma unroll
        for (int r = 0; r < 4; r++) {
            const int idx = tid + r * 256;   // 0..1023
            const int row = idx >> 3;        // 0..127
            const int c4  = (idx & 7) * 4;   // 0..28
            float4 v = *(const float4*)&Qh[(size_t)(q0 + row) * HD + d0 + c4];
            Qs[c4 + 0][row] = v.x; Qs[c4 + 1][row] = v.y;
            Qs[c4 + 2][row] = v.z; Qs[c4 + 3][row] = v.w;
            float4 u = *(const float4*)&Kh[(size_t)(k0 + row) * HD + d0 + c4];
            Ks[c4 + 0][row] = u.x; Ks[c4 + 1][row] = u.y;
            Ks[c4 + 2][row] = u.z; Ks[c4 + 3][row] = u.w;
        }
        __syncthreads();

#pragma unroll
        for (int dd = 0; dd < 32; dd++) {
            float a[8], b[8];
            *(float4*)(a)     = *(const float4*)&Qs[dd][trow * 8];
            *(float4*)(a + 4) = *(const float4*)&Qs[dd][trow * 8 + 4];
            *(float4*)(b)     = *(const float4*)&Ks[dd][tcol * 8];
            *(float4*)(b + 4) = *(const float4*)&Ks[dd][tcol * 8 + 4];
#pragma unroll
            for (int i = 0; i < 8; i++)
#pragma unroll
                for (int j = 0; j < 8; j++)
                    acc[i][j] = fmaf(a[i], b[j], acc[i][j]);
        }
        __syncthreads();
    }

    const float scale = 0.125f;  // 1/sqrt(64)
#pragma unroll
    for (int i = 0; i < 8; i++) {
        const int row = q0 + trow * 8 + i;
#pragma unroll
        for (int j0 = 0; j0 < 8; j0 += 4) {
            const int col = k0 + tcol * 8 + j0;
            float4 o;
            o.x = acc[i][j0 + 0] * scale;
            o.y = acc[i][j0 + 1] * scale;
            o.z = acc[i][j0 + 2] * scale;
            o.w = acc[i][j0 + 3] * scale;
            *(float4*)&Sc[(size_t)row * SQ + col] = o;
        }
    }
}

// ============================================================
// Per-head V column sums
// ============================================================
__global__ __launch_bounds__(256) void vsum_kernel()
{
    const int h = blockIdx.x;
    const int t = threadIdx.x & 63;
    const int g = threadIdx.x >> 6;   // 0..3
    const float* Vh = g_V + (size_t)h * SQ * HD;
    float s = 0.0f;
    for (int r = g * 512; r < (g + 1) * 512; ++r)
        s += Vh[(size_t)r * HD + t];
    __shared__ float red[4][64];
    red[g][t] = s;
    __syncthreads();
    if (g == 0)
        g_vsum[h * HD + t] = red[0][t] + red[1][t] + red[2][t] + red[3][t];
}

// ============================================================
// Top-16 + sparse softmax + PV gather. One warp per (h, q).
// out = sum_i (p_i - p0) V[idx_i] + p0 * vsum,  p0 = exp(-m)/Z
// ============================================================
__global__ __launch_bounds__(128) void topk_attend()
{
    const unsigned FULL = 0xffffffffu;
    const int gwarp = (blockIdx.x * 128 + threadIdx.x) >> 5;
    const int lane  = threadIdx.x & 31;
    const int h = gwarp >> 11;       // / 2048
    const int q = gwarp & 2047;

    const float* row = g_scores + ((size_t)h * SQ + q) * SQ;

    // ---- per-lane sorted (desc) top-16 over 64 strided elements ----
    float lv[16];
    int   li[16];
#pragma unroll
    for (int i = 0; i < 16; i++) { lv[i] = -1e30f; li[i] = 0; }

#pragma unroll 4
    for (int c = 0; c < 16; c++) {
        const int base = c * 128 + lane * 4;
        float4 v4 = *(const float4*)&row[base];
        float vals[4] = {v4.x, v4.y, v4.z, v4.w};
#pragma unroll
        for (int j = 0; j < 4; j++) {
            const float val = vals[j];
            if (val > lv[15]) {
                lv[15] = val; li[15] = base + j;
#pragma unroll
                for (int p = 15; p >= 1; --p) {
                    if (lv[p] > lv[p - 1]) {
                        float tv = lv[p]; lv[p] = lv[p - 1]; lv[p - 1] = tv;
                        int   ti = li[p]; li[p] = li[p - 1]; li[p - 1] = ti;
                    }
                }
            }
        }
    }

    // ---- 16-round warp argmax merge; lane r keeps the r-th largest ----
    float fv = -1e30f;
    int   fi = 0;
    for (int r = 0; r < 16; r++) {
        float bv = lv[0]; int bi = li[0]; int bl = lane;
#pragma unroll
        for (int off = 16; off > 0; off >>= 1) {
            float ov = __shfl_down_sync(FULL, bv, off);
            int   oi = __shfl_down_sync(FULL, bi, off);
            int   ol = __shfl_down_sync(FULL, bl, off);
            if (ov > bv) { bv = ov; bi = oi; bl = ol; }
        }
        bv = __shfl_sync(FULL, bv, 0);
        bi = __shfl_sync(FULL, bi, 0);
        bl = __shfl_sync(FULL, bl, 0);
        if (lane == bl) {   // pop winner's head
#pragma unroll
            for (int p = 0; p < 15; p++) { lv[p] = lv[p + 1]; li[p] = li[p + 1]; }
            lv[15] = -1e30f;
        }
        if (lane == r) { fv = bv; fi = bi; }
    }

    // ---- sparse softmax (zeros participate) ----
    float m = __shfl_sync(FULL, fv, 0);   // sorted desc -> lane 0 = max
    m = fmaxf(m, 0.0f);
    float e = (lane < 16) ? expf(fv - m) : 0.0f;
    float z = e;
#pragma unroll
    for (int off = 16; off > 0; off >>= 1)
        z += __shfl_xor_sync(FULL, z, off);
    const float e0 = expf(-m);
    const float Z  = z + (float)(SQ - FACT) * e0;
    const float p0 = e0 / Z;
    const float w  = e / Z - p0;

    // ---- gather 16 V rows + p0 * vsum ----
    const float* Vh = g_V + (size_t)h * SQ * HD;
    float acc0 = p0 * g_vsum[h * HD + lane];
    float acc1 = p0 * g_vsum[h * HD + lane + 32];
#pragma unroll
    for (int i = 0; i < 16; i++) {
        const float wi  = __shfl_sync(FULL, w,  i);
        const int   idx = __shfl_sync(FULL, fi, i);
        const float* vr = Vh + (size_t)idx * HD;
        acc0 = fmaf(wi, vr[lane],      acc0);
        acc1 = fmaf(wi, vr[lane + 32], acc1);
    }
    float* o = g_attn + (size_t)q * DIM + h * HD;
    o[lane]      = acc0;
    o[lane + 32] = acc1;
}

// ============================================================
extern "C" void kernel_launch(void* const* d_in, const int* in_sizes, int n_in,
                              void* d_out, int out_size)
{
    const float* x  = (const float*)d_in[0];
    const float* Wq = (const float*)d_in[1];
    const float* bq = (const float*)d_in[2];
    const float* Wk = (const float*)d_in[3];
    const float* bk = (const float*)d_in[4];
    const float* Wv = (const float*)d_in[5];
    const float* bv = (const float*)d_in[6];
    const float* Wo = (const float*)d_in[7];
    const float* bo = (const float*)d_in[8];
    float* out = (float*)d_out;

    float *Qp, *Kp, *Vp, *attnp;
    cudaGetSymbolAddress((void**)&Qp,    g_Q);
    cudaGetSymbolAddress((void**)&Kp,    g_K);
    cudaGetSymbolAddress((void**)&Vp,    g_V);
    cudaGetSymbolAddress((void**)&attnp, g_attn);

    dim3 gProj(DIM / 128, SQ / 128);      // (8, 16)
    sgemm_bias<<<gProj, 256>>>(x, Wq, bq, Qp, SQ, DIM, DIM, 1);
    sgemm_bias<<<gProj, 256>>>(x, Wk, bk, Kp, SQ, DIM, DIM, 1);
    sgemm_bias<<<gProj, 256>>>(x, Wv, bv, Vp, SQ, DIM, DIM, 1);

    vsum_kernel<<<NH, 256>>>();

    dim3 gSc(SQ / 128, SQ / 128, NH);     // (16, 16, 16)
    scores_kernel<<<gSc, 256>>>();

    topk_attend<<<(NH * SQ) / 4, 128>>>();

    sgemm_bias<<<gProj, 256>>>(attnp, Wo, bo, out, SQ, DIM, DIM, 0);
}

// round 3
// speedup vs baseline: 1.0483x; 1.0483x over previous
#include <cuda_runtime.h>
#include <math.h>

#define SQ   2048
#define DIM  1024
#define NH   16
#define HD   64
#define FACT 16

// ---- scratch (device globals: the sanctioned no-alloc scratch path) ----
__device__ float g_Q[NH * SQ * HD];             // 8 MB  [h][s][hd]
__device__ float g_K[NH * SQ * HD];             // 8 MB
__device__ float g_V[NH * SQ * HD];             // 8 MB
__device__ float g_scores[(size_t)NH * SQ * SQ]; // 256 MB [h][q][k]
__device__ float g_vsum[NH * HD];
__device__ float g_attn[SQ * DIM];              // 8 MB  [s][d]

// ============================================================
// Generic fp32 GEMM: C[M,N] = A[M,K] @ B[K,N] + bias[N]
// 128x128 tile, BK=8, 256 threads, 8x8 microtile.
// remap!=0 -> write C in [h][row][t] layout (h=col/64, t=col%64)
// ============================================================
__global__ __launch_bounds__(256) void sgemm_bias(
    const float* __restrict__ A, const float* __restrict__ B,
    const float* __restrict__ bias, float* __restrict__ C,
    int M, int N, int K, int remap)
{
    __shared__ float As[8][128];
    __shared__ float Bs[8][128];

    const int tid  = threadIdx.x;
    const int r0   = blockIdx.y * 128;
    const int n0   = blockIdx.x * 128;
    const int trow = tid / 16;          // 0..15
    const int tcol = tid % 16;          // 0..15

    const int arow = tid >> 1;          // 0..127
    const int ac4  = (tid & 1) * 4;     // 0 or 4
    const int brow = tid >> 5;          // 0..7
    const int bc4  = (tid & 31) * 4;    // 0..124

    float acc[8][8];
#pragma unroll
    for (int i = 0; i < 8; i++)
#pragma unroll
        for (int j = 0; j < 8; j++) acc[i][j] = 0.0f;

    for (int k0 = 0; k0 < K; k0 += 8) {
        float4 av = *(const float4*)&A[(size_t)(r0 + arow) * K + k0 + ac4];
        As[ac4 + 0][arow] = av.x;
        As[ac4 + 1][arow] = av.y;
        As[ac4 + 2][arow] = av.z;
        As[ac4 + 3][arow] = av.w;
        *(float4*)&Bs[brow][bc4] =
            *(const float4*)&B[(size_t)(k0 + brow) * N + n0 + bc4];
        __syncthreads();

#pragma unroll
        for (int kk = 0; kk < 8; kk++) {
            float a[8], b[8];
            *(float4*)(a)     = *(const float4*)&As[kk][trow * 8];
            *(float4*)(a + 4) = *(const float4*)&As[kk][trow * 8 + 4];
            *(float4*)(b)     = *(const float4*)&Bs[kk][tcol * 8];
            *(float4*)(b + 4) = *(const float4*)&Bs[kk][tcol * 8 + 4];
#pragma unroll
            for (int i = 0; i < 8; i++)
#pragma unroll
                for (int j = 0; j < 8; j++)
                    acc[i][j] = fmaf(a[i], b[j], acc[i][j]);
        }
        __syncthreads();
    }

#pragma unroll
    for (int i = 0; i < 8; i++) {
        const int row = r0 + trow * 8 + i;
#pragma unroll
        for (int j0 = 0; j0 < 8; j0 += 4) {
            const int col = n0 + tcol * 8 + j0;
            float4 o;
            o.x = acc[i][j0 + 0] + bias[col + 0];
            o.y = acc[i][j0 + 1] + bias[col + 1];
            o.z = acc[i][j0 + 2] + bias[col + 2];
            o.w = acc[i][j0 + 3] + bias[col + 3];
            if (remap) {
                const int h = col >> 6;
                const int t = col & 63;
                *(float4*)&C[((size_t)h * SQ + row) * HD + t] = o;
            } else {
                *(float4*)&C[(size_t)row * N + col] = o;
            }
        }
    }
}

// ============================================================
// Scores: g_scores[h][q][k] = (Q[h][q] . K[h][k]) / 8
// 128x128 tile per block, full K-dim=64 in two 32-deep passes.
// ============================================================
__global__ __launch_bounds__(256) void scores_kernel()
{
    __shared__ float Qs[32][128];
    __shared__ float Ks[32][128];

    const int h  = blockIdx.z;
    const float* Qh = g_Q + (size_t)h * SQ * HD;
    const float* Kh = g_K + (size_t)h * SQ * HD;
    float* Sc = g_scores + (size_t)h * SQ * SQ;

    const int q0 = blockIdx.y * 128;
    const int k0 = blockIdx.x * 128;
    const int tid  = threadIdx.x;
    const int trow = tid / 16;
    const int tcol = tid % 16;

    float acc[8][8];
#pragma unroll
    for (int i = 0; i < 8; i++)
#pragma unroll
        for (int j = 0; j < 8; j++) acc[i][j] = 0.0f;

    for (int d0 = 0; d0 < HD; d0 += 32) {
#pragma unroll
        for (int r = 0; r < 4; r++) {
            const int idx = tid + r * 256;   // 0..1023
            const int row = idx >> 3;        // 0..127
            const int c4  = (idx & 7) * 4;   // 0..28
            float4 v = *(const float4*)&Qh[(size_t)(q0 + row) * HD + d0 + c4];
            Qs[c4 + 0][row] = v.x; Qs[c4 + 1][row] = v.y;
            Qs[c4 + 2][row] = v.z; Qs[c4 + 3][row] = v.w;
            float4 u = *(const float4*)&Kh[(size_t)(k0 + row) * HD + d0 + c4];
            Ks[c4 + 0][row] = u.x; Ks[c4 + 1][row] = u.y;
            Ks[c4 + 2][row] = u.z; Ks[c4 + 3][row] = u.w;
        }
        __syncthreads();

#pragma unroll
        for (int dd = 0; dd < 32; dd++) {
            float a[8], b[8];
            *(float4*)(a)     = *(const float4*)&Qs[dd][trow * 8];
            *(float4*)(a + 4) = *(const float4*)&Qs[dd][trow * 8 + 4];
            *(float4*)(b)     = *(const float4*)&Ks[dd][tcol * 8];
            *(float4*)(b + 4) = *(const float4*)&Ks[dd][tcol * 8 + 4];
#pragma unroll
            for (int i = 0; i < 8; i++)
#pragma unroll
                for (int j = 0; j < 8; j++)
                    acc[i][j] = fmaf(a[i], b[j], acc[i][j]);
        }
        __syncthreads();
    }

    const float scale = 0.125f;  // 1/sqrt(64)
#pragma unroll
    for (int i = 0; i < 8; i++) {
        const int row = q0 + trow * 8 + i;
#pragma unroll
        for (int j0 = 0; j0 < 8; j0 += 4) {
            const int col = k0 + tcol * 8 + j0;
            float4 o;
            o.x = acc[i][j0 + 0] * scale;
            o.y = acc[i][j0 + 1] * scale;
            o.z = acc[i][j0 + 2] * scale;
            o.w = acc[i][j0 + 3] * scale;
            *(float4*)&Sc[(size_t)row * SQ + col] = o;
        }
    }
}

// ============================================================
// Per-head V column sums
// ============================================================
__global__ __launch_bounds__(256) void vsum_kernel()
{
    const int h = blockIdx.x;
    const int t = threadIdx.x & 63;
    const int g = threadIdx.x >> 6;   // 0..3
    const float* Vh = g_V + (size_t)h * SQ * HD;
    float s = 0.0f;
    for (int r = g * 512; r < (g + 1) * 512; ++r)
        s += Vh[(size_t)r * HD + t];
    __shared__ float red[4][64];
    red[g][t] = s;
    __syncthreads();
    if (g == 0)
        g_vsum[h * HD + t] = red[0][t] + red[1][t] + red[2][t] + red[3][t];
}

// ============================================================
// Top-16 + sparse softmax + PV gather. One warp per (h, q).
// out = sum_i (p_i - p0) V[idx_i] + p0 * vsum,  p0 = exp(-m)/Z
// ============================================================
__global__ __launch_bounds__(128) void topk_attend()
{
    const unsigned FULL = 0xffffffffu;
    const int gwarp = (blockIdx.x * 128 + threadIdx.x) >> 5;
    const int lane  = threadIdx.x & 31;
    const int h = gwarp >> 11;       // / 2048
    const int q = gwarp & 2047;

    const float* row = g_scores + ((size_t)h * SQ + q) * SQ;

    // ---- per-lane sorted (desc) top-16 over 64 strided elements ----
    float lv[16];
    int   li[16];
#pragma unroll
    for (int i = 0; i < 16; i++) { lv[i] = -1e30f; li[i] = 0; }

#pragma unroll 4
    for (int c = 0; c < 16; c++) {
        const int base = c * 128 + lane * 4;
        float4 v4 = *(const float4*)&row[base];
        float vals[4] = {v4.x, v4.y, v4.z, v4.w};
#pragma unroll
        for (int j = 0; j < 4; j++) {
            const float val = vals[j];
            if (val > lv[15]) {
                lv[15] = val; li[15] = base + j;
#pragma unroll
                for (int p = 15; p >= 1; --p) {
                    if (lv[p] > lv[p - 1]) {
                        float tv = lv[p]; lv[p] = lv[p - 1]; lv[p - 1] = tv;
                        int   ti = li[p]; li[p] = li[p - 1]; li[p - 1] = ti;
                    }
                }
            }
        }
    }

    // ---- 16-round warp argmax merge; lane r keeps the r-th largest ----
    float fv = -1e30f;
    int   fi = 0;
    for (int r = 0; r < 16; r++) {
        float bv = lv[0]; int bi = li[0]; int bl = lane;
#pragma unroll
        for (int off = 16; off > 0; off >>= 1) {
            float ov = __shfl_down_sync(FULL, bv, off);
            int   oi = __shfl_down_sync(FULL, bi, off);
            int   ol = __shfl_down_sync(FULL, bl, off);
            if (ov > bv) { bv = ov; bi = oi; bl = ol; }
        }
        bv = __shfl_sync(FULL, bv, 0);
        bi = __shfl_sync(FULL, bi, 0);
        bl = __shfl_sync(FULL, bl, 0);
        if (lane == bl) {   // pop winner's head
#pragma unroll
            for (int p = 0; p < 15; p++) { lv[p] = lv[p + 1]; li[p] = li[p + 1]; }
            lv[15] = -1e30f;
        }
        if (lane == r) { fv = bv; fi = bi; }
    }

    // ---- sparse softmax (zeros participate) ----
    float m = __shfl_sync(FULL, fv, 0);   // sorted desc -> lane 0 = max
    m = fmaxf(m, 0.0f);
    float e = (lane < 16) ? expf(fv - m) : 0.0f;
    float z = e;
#pragma unroll
    for (int off = 16; off > 0; off >>= 1)
        z += __shfl_xor_sync(FULL, z, off);
    const float e0 = expf(-m);
    const float Z  = z + (float)(SQ - FACT) * e0;
    const float p0 = e0 / Z;
    const float w  = e / Z - p0;

    // ---- gather 16 V rows + p0 * vsum ----
    const float* Vh = g_V + (size_t)h * SQ * HD;
    float acc0 = p0 * g_vsum[h * HD + lane];
    float acc1 = p0 * g_vsum[h * HD + lane + 32];
#pragma unroll
    for (int i = 0; i < 16; i++) {
        const float wi  = __shfl_sync(FULL, w,  i);
        const int   idx = __shfl_sync(FULL, fi, i);
        const float* vr = Vh + (size_t)idx * HD;
        acc0 = fmaf(wi, vr[lane],      acc0);
        acc1 = fmaf(wi, vr[lane + 32], acc1);
    }
    float* o = g_attn + (size_t)q * DIM + h * HD;
    o[lane]      = acc0;
    o[lane + 32] = acc1;
}

// ============================================================
extern "C" void kernel_launch(void* const* d_in, const int* in_sizes, int n_in,
                              void* d_out, int out_size)
{
    const float* x  = (const float*)d_in[0];
    const float* Wq = (const float*)d_in[1];
    const float* bq = (const float*)d_in[2];
    const float* Wk = (const float*)d_in[3];
    const float* bk = (const float*)d_in[4];
    const float* Wv = (const float*)d_in[5];
    const float* bv = (const float*)d_in[6];
    const float* Wo = (const float*)d_in[7];
    const float* bo = (const float*)d_in[8];
    float* out = (float*)d_out;

    float *Qp, *Kp, *Vp, *attnp;
    cudaGetSymbolAddress((void**)&Qp,    g_Q);
    cudaGetSymbolAddress((void**)&Kp,    g_K);
    cudaGetSymbolAddress((void**)&Vp,    g_V);
    cudaGetSymbolAddress((void**)&attnp, g_attn);

    dim3 gProj(DIM / 128, SQ / 128);      // (8, 16)
    sgemm_bias<<<gProj, 256>>>(x, Wq, bq, Qp, SQ, DIM, DIM, 1);
    sgemm_bias<<<gProj, 256>>>(x, Wk, bk, Kp, SQ, DIM, DIM, 1);
    sgemm_bias<<<gProj, 256>>>(x, Wv, bv, Vp, SQ, DIM, DIM, 1);

    vsum_kernel<<<NH, 256>>>();

    dim3 gSc(SQ / 128, SQ / 128, NH);     // (16, 16, 16)
    scores_kernel<<<gSc, 256>>>();

    topk_attend<<<(NH * SQ) / 4, 128>>>();

    sgemm_bias<<<gProj, 256>>>(attnp, Wo, bo, out, SQ, DIM, DIM, 0);
}

// round 5
// speedup vs baseline: 1.3775x; 1.3140x over previous
#include <cuda_runtime.h>
#include <math.h>

#define SQ   2048
#define DIM  1024
#define NH   16
#define HD   64
#define FACT 16

// ---- scratch (device globals: the sanctioned no-alloc scratch path) ----
__device__ float g_Q[NH * SQ * HD];              // 8 MB  [h][s][hd]
__device__ float g_K[NH * SQ * HD];              // 8 MB
__device__ float g_V[NH * SQ * HD];              // 8 MB
__device__ float g_scores[(size_t)NH * SQ * SQ]; // 256 MB [h][q][k]
__device__ float g_vsum[NH * HD];
__device__ float g_attn[SQ * DIM];               // 8 MB  [s][d]
__device__ float g_WT[4 * DIM * DIM];            // 16 MB transposed weights

// ============================================================
// helpers
// ============================================================
__device__ __forceinline__ unsigned f2tf(float f) {
    unsigned u;
    asm("cvt.rna.tf32.f32 %0, %1;" : "=r"(u) : "f"(f));
    return u;
}

__device__ __forceinline__ void mma_tf32(float* c, const unsigned* a, const unsigned* b) {
    asm volatile(
        "mma.sync.aligned.m16n8k8.row.col.f32.tf32.tf32.f32 "
        "{%0,%1,%2,%3}, {%4,%5,%6,%7}, {%8,%9}, {%0,%1,%2,%3};"
        : "+f"(c[0]), "+f"(c[1]), "+f"(c[2]), "+f"(c[3])
        : "r"(a[0]), "r"(a[1]), "r"(a[2]), "r"(a[3]),
          "r"(b[0]), "r"(b[1]));
}

// ============================================================
// 1024x1024 fp32 transpose (for weights -> NT form)
// ============================================================
__global__ __launch_bounds__(256) void transpose1024(
    const float* __restrict__ S, float* __restrict__ D)
{
    __shared__ float tile[32][33];
    int x = blockIdx.x * 32 + threadIdx.x;
    int y = blockIdx.y * 32 + threadIdx.y;
#pragma unroll
    for (int j = 0; j < 32; j += 8)
        tile[threadIdx.y + j][threadIdx.x] = S[(size_t)(y + j) * DIM + x];
    __syncthreads();
    x = blockIdx.y * 32 + threadIdx.x;
    y = blockIdx.x * 32 + threadIdx.y;
#pragma unroll
    for (int j = 0; j < 32; j += 8)
        D[(size_t)(y + j) * DIM + x] = tile[threadIdx.x][threadIdx.y + j];
}

// ============================================================
// Unified NT 3xTF32 tensor-core GEMM (fp32-accurate):
//   C[m][n] = alpha * sum_k A[m][k]*B[n][k]  (+ bias[n])
// Split each operand v = hi + lo (tf32 planes in smem) and do
//   C += Ahi*Bhi + Ahi*Blo + Alo*Bhi.
// 128x128 block tile, BK=32, 8 warps of 64x32 (m16n8k8 mma).
// remap!=0 -> write C in [h][row][t] layout (h=col/64, t=col%64).
// blockIdx.z batches over heads via str{A,B,C}.
// ============================================================
#define BKT 32
#define SMS 36   // smem row stride (BKT + 4): conflict-free for frag LDS
#define SM_PLANE (128 * SMS)
#define SMEM_BYTES (4 * SM_PLANE * 4)

__global__ __launch_bounds__(256) void nt_tf32x3_gemm(
    const float* __restrict__ A, const float* __restrict__ B,
    const float* __restrict__ bias, float* __restrict__ C,
    int K, int lda, int ldb, int ldc,
    float alpha, int remap,
    long strA, long strB, long strC)
{
    extern __shared__ unsigned sm[];
    unsigned* AsH = sm;
    unsigned* AsL = sm + SM_PLANE;
    unsigned* BsH = sm + 2 * SM_PLANE;
    unsigned* BsL = sm + 3 * SM_PLANE;

    A += (size_t)blockIdx.z * strA;
    B += (size_t)blockIdx.z * strB;
    C += (size_t)blockIdx.z * strC;

    const int tid  = threadIdx.x;
    const int lane = tid & 31;
    const int wid  = tid >> 5;
    const int wm   = (wid >> 2) * 64;   // warp m-offset (0,64)
    const int wn   = (wid & 3) * 32;    // warp n-offset (0,32,64,96)
    const int g    = lane >> 2;         // groupID 0..7
    const int t    = lane & 3;          // threadID_in_group 0..3

    const int m0 = blockIdx.y * 128;
    const int n0 = blockIdx.x * 128;

    float acc[4][4][4];
#pragma unroll
    for (int mt = 0; mt < 4; mt++)
#pragma unroll
        for (int nt = 0; nt < 4; nt++)
#pragma unroll
            for (int e = 0; e < 4; e++) acc[mt][nt][e] = 0.0f;

    for (int k0 = 0; k0 < K; k0 += BKT) {
        // stage 128x32 of A and B into hi/lo tf32 planes
#pragma unroll
        for (int i = 0; i < 4; i++) {
            const int idx = tid + i * 256;
            const int row = idx >> 3;
            const int kc  = (idx & 7) << 2;
            const int so  = row * SMS + kc;

            float4 av = *(const float4*)&A[(size_t)(m0 + row) * lda + k0 + kc];
            uint4 ah, al;
            ah.x = f2tf(av.x); al.x = f2tf(av.x - __uint_as_float(ah.x));
            ah.y = f2tf(av.y); al.y = f2tf(av.y - __uint_as_float(ah.y));
            ah.z = f2tf(av.z); al.z = f2tf(av.z - __uint_as_float(ah.z));
            ah.w = f2tf(av.w); al.w = f2tf(av.w - __uint_as_float(ah.w));
            *(uint4*)&AsH[so] = ah;
            *(uint4*)&AsL[so] = al;

            float4 bv = *(const float4*)&B[(size_t)(n0 + row) * ldb + k0 + kc];
            uint4 bh, bl;
            bh.x = f2tf(bv.x); bl.x = f2tf(bv.x - __uint_as_float(bh.x));
            bh.y = f2tf(bv.y); bl.y = f2tf(bv.y - __uint_as_float(bh.y));
            bh.z = f2tf(bv.z); bl.z = f2tf(bv.z - __uint_as_float(bh.z));
            bh.w = f2tf(bv.w); bl.w = f2tf(bv.w - __uint_as_float(bh.w));
            *(uint4*)&BsH[so] = bh;
            *(uint4*)&BsL[so] = bl;
        }
        __syncthreads();

#pragma unroll
        for (int ks = 0; ks < BKT; ks += 8) {
            unsigned afh[4][4], afl[4][4], bfh[4][2], bfl[4][2];
#pragma unroll
            for (int mt = 0; mt < 4; mt++) {
                const int off = (wm + mt * 16 + g) * SMS + ks + t;
                afh[mt][0] = AsH[off];
                afh[mt][1] = AsH[off + 8 * SMS];
                afh[mt][2] = AsH[off + 4];
                afh[mt][3] = AsH[off + 8 * SMS + 4];
                afl[mt][0] = AsL[off];
                afl[mt][1] = AsL[off + 8 * SMS];
                afl[mt][2] = AsL[off + 4];
                afl[mt][3] = AsL[off + 8 * SMS + 4];
            }
#pragma unroll
            for (int nt = 0; nt < 4; nt++) {
                const int off = (wn + nt * 8 + g) * SMS + ks + t;
                bfh[nt][0] = BsH[off];
                bfh[nt][1] = BsH[off + 4];
                bfl[nt][0] = BsL[off];
                bfl[nt][1] = BsL[off + 4];
            }
#pragma unroll
            for (int mt = 0; mt < 4; mt++)
#pragma unroll
                for (int nt = 0; nt < 4; nt++) {
                    mma_tf32(acc[mt][nt], afl[mt], bfh[nt]);
                    mma_tf32(acc[mt][nt], afh[mt], bfl[nt]);
                    mma_tf32(acc[mt][nt], afh[mt], bfh[nt]);
                }
        }
        __syncthreads();
    }

    // epilogue: c0=(g,2t) c1=(g,2t+1) c2=(g+8,2t) c3=(g+8,2t+1)
#pragma unroll
    for (int mt = 0; mt < 4; mt++) {
        const int rowA = m0 + wm + mt * 16 + g;
        const int rowB = rowA + 8;
#pragma unroll
        for (int nt = 0; nt < 4; nt++) {
            const int col = n0 + wn + nt * 8 + 2 * t;
            float bx = 0.0f, by = 0.0f;
            if (bias) { bx = bias[col]; by = bias[col + 1]; }
            float2 lo, hi;
            lo.x = acc[mt][nt][0] * alpha + bx;
            lo.y = acc[mt][nt][1] * alpha + by;
            hi.x = acc[mt][nt][2] * alpha + bx;
            hi.y = acc[mt][nt][3] * alpha + by;
            if (remap) {
                const int h = col >> 6;
                const int tc = col & 63;
                *(float2*)&C[((size_t)h * SQ + rowA) * HD + tc] = lo;
                *(float2*)&C[((size_t)h * SQ + rowB) * HD + tc] = hi;
            } else {
                *(float2*)&C[(size_t)rowA * ldc + col] = lo;
                *(float2*)&C[(size_t)rowB * ldc + col] = hi;
            }
        }
    }
}

// ============================================================
// Per-head V column sums
// ============================================================
__global__ __launch_bounds__(256) void vsum_kernel()
{
    const int h = blockIdx.x;
    const int t = threadIdx.x & 63;
    const int g = threadIdx.x >> 6;   // 0..3
    const float* Vh = g_V + (size_t)h * SQ * HD;
    float s = 0.0f;
    for (int r = g * 512; r < (g + 1) * 512; ++r)
        s += Vh[(size_t)r * HD + t];
    __shared__ float red[4][64];
    red[g][t] = s;
    __syncthreads();
    if (g == 0)
        g_vsum[h * HD + t] = red[0][t] + red[1][t] + red[2][t] + red[3][t];
}

// ============================================================
// Top-16 + sparse softmax + PV gather. One warp per (h, q).
// out = sum_i (p_i - p0) V[idx_i] + p0 * vsum,  p0 = exp(-m)/Z
// ============================================================
__global__ __launch_bounds__(128) void topk_attend()
{
    const unsigned FULL = 0xffffffffu;
    const int gwarp = (blockIdx.x * 128 + threadIdx.x) >> 5;
    const int lane  = threadIdx.x & 31;
    const int h = gwarp >> 11;       // / 2048
    const int q = gwarp & 2047;

    const float* row = g_scores + ((size_t)h * SQ + q) * SQ;

    // ---- per-lane sorted (desc) top-16 over 64 strided elements ----
    float lv[16];
    int   li[16];
#pragma unroll
    for (int i = 0; i < 16; i++) { lv[i] = -1e30f; li[i] = 0; }

#pragma unroll 4
    for (int c = 0; c < 16; c++) {
        const int base = c * 128 + lane * 4;
        float4 v4 = *(const float4*)&row[base];
        float vals[4] = {v4.x, v4.y, v4.z, v4.w};
#pragma unroll
        for (int j = 0; j < 4; j++) {
            const float val = vals[j];
            if (val > lv[15]) {
                lv[15] = val; li[15] = base + j;
#pragma unroll
                for (int p = 15; p >= 1; --p) {
                    if (lv[p] > lv[p - 1]) {
                        float tv = lv[p]; lv[p] = lv[p - 1]; lv[p - 1] = tv;
                        int   ti = li[p]; li[p] = li[p - 1]; li[p - 1] = ti;
                    }
                }
            }
        }
    }

    // ---- 16-round warp argmax merge; lane r keeps the r-th largest ----
    float fv = -1e30f;
    int   fi = 0;
    for (int r = 0; r < 16; r++) {
        float bv = lv[0]; int bi = li[0]; int bl = lane;
#pragma unroll
        for (int off = 16; off > 0; off >>= 1) {
            float ov = __shfl_down_sync(FULL, bv, off);
            int   oi = __shfl_down_sync(FULL, bi, off);
            int   ol = __shfl_down_sync(FULL, bl, off);
            if (ov > bv) { bv = ov; bi = oi; bl = ol; }
        }
        bv = __shfl_sync(FULL, bv, 0);
        bi = __shfl_sync(FULL, bi, 0);
        bl = __shfl_sync(FULL, bl, 0);
        if (lane == bl) {   // pop winner's head
#pragma unroll
            for (int p = 0; p < 15; p++) { lv[p] = lv[p + 1]; li[p] = li[p + 1]; }
            lv[15] = -1e30f;
        }
        if (lane == r) { fv = bv; fi = bi; }
    }

    // ---- sparse softmax (zeros participate) ----
    float m = __shfl_sync(FULL, fv, 0);   // sorted desc -> lane 0 = max
    m = fmaxf(m, 0.0f);
    float e = (lane < 16) ? expf(fv - m) : 0.0f;
    float z = e;
#pragma unroll
    for (int off = 16; off > 0; off >>= 1)
        z += __shfl_xor_sync(FULL, z, off);
    const float e0 = expf(-m);
    const float Z  = z + (float)(SQ - FACT) * e0;
    const float p0 = e0 / Z;
    const float w  = e / Z - p0;

    // ---- gather 16 V rows + p0 * vsum ----
    const float* Vh = g_V + (size_t)h * SQ * HD;
    float acc0 = p0 * g_vsum[h * HD + lane];
    float acc1 = p0 * g_vsum[h * HD + lane + 32];
#pragma unroll
    for (int i = 0; i < 16; i++) {
        const float wi  = __shfl_sync(FULL, w,  i);
        const int   idx = __shfl_sync(FULL, fi, i);
        const float* vr = Vh + (size_t)idx * HD;
        acc0 = fmaf(wi, vr[lane],      acc0);
        acc1 = fmaf(wi, vr[lane + 32], acc1);
    }
    float* o = g_attn + (size_t)q * DIM + h * HD;
    o[lane]      = acc0;
    o[lane + 32] = acc1;
}

// ============================================================
extern "C" void kernel_launch(void* const* d_in, const int* in_sizes, int n_in,
                              void* d_out, int out_size)
{
    const float* x  = (const float*)d_in[0];
    const float* Wq = (const float*)d_in[1];
    const float* bq = (const float*)d_in[2];
    const float* Wk = (const float*)d_in[3];
    const float* bk = (const float*)d_in[4];
    const float* Wv = (const float*)d_in[5];
    const float* bv = (const float*)d_in[6];
    const float* Wo = (const float*)d_in[7];
    const float* bo = (const float*)d_in[8];
    float* out = (float*)d_out;

    float *Qp, *Kp, *Vp, *attnp, *scoresp, *WTp;
    cudaGetSymbolAddress((void**)&Qp,      g_Q);
    cudaGetSymbolAddress((void**)&Kp,      g_K);
    cudaGetSymbolAddress((void**)&Vp,      g_V);
    cudaGetSymbolAddress((void**)&attnp,   g_attn);
    cudaGetSymbolAddress((void**)&scoresp, g_scores);
    cudaGetSymbolAddress((void**)&WTp,     g_WT);

    float* WqT = WTp;
    float* WkT = WTp + (size_t)DIM * DIM;
    float* WvT = WTp + 2 * (size_t)DIM * DIM;
    float* WoT = WTp + 3 * (size_t)DIM * DIM;

    static int smem_set = 0;
    if (!smem_set) {
        cudaFuncSetAttribute(nt_tf32x3_gemm,
                             cudaFuncAttributeMaxDynamicSharedMemorySize,
                             SMEM_BYTES);
        smem_set = 1;
    }

    dim3 gT(DIM / 32, DIM / 32);
    dim3 bT(32, 8);
    transpose1024<<<gT, bT>>>(Wq, WqT);
    transpose1024<<<gT, bT>>>(Wk, WkT);
    transpose1024<<<gT, bT>>>(Wv, WvT);
    transpose1024<<<gT, bT>>>(Wo, WoT);

    dim3 gProj(DIM / 128, SQ / 128, 1);   // (8, 16, 1)
    nt_tf32x3_gemm<<<gProj, 256, SMEM_BYTES>>>(x, WqT, bq, Qp, DIM, DIM, DIM, DIM, 1.0f, 1, 0, 0, 0);
    nt_tf32x3_gemm<<<gProj, 256, SMEM_BYTES>>>(x, WkT, bk, Kp, DIM, DIM, DIM, DIM, 1.0f, 1, 0, 0, 0);
    nt_tf32x3_gemm<<<gProj, 256, SMEM_BYTES>>>(x, WvT, bv, Vp, DIM, DIM, DIM, DIM, 1.0f, 1, 0, 0, 0);

    vsum_kernel<<<NH, 256>>>();

    dim3 gSc(SQ / 128, SQ / 128, NH);     // (16, 16, 16)
    nt_tf32x3_gemm<<<gSc, 256, SMEM_BYTES>>>(Qp, Kp, nullptr, scoresp,
                                             HD, HD, HD, SQ, 0.125f, 0,
                                             (long)SQ * HD, (long)SQ * HD, (long)SQ * SQ);

    topk_attend<<<(NH * SQ) / 4, 128>>>();

    nt_tf32x3_gemm<<<gProj, 256, SMEM_BYTES>>>(attnp, WoT, bo, out, DIM, DIM, DIM, DIM, 1.0f, 0, 0, 0, 0);
}